// round 5
// baseline (speedup 1.0000x reference)
#include <cuda_runtime.h>
#include <cstdint>

#define UNITS  512
#define NIN    256
#define NBATCH 512
#define JT 32          // j-columns per CTA
#define BT 8           // batches per CTA
#define NB 2           // batches per thread
#define NTHR 128       // 4 warps: 32 j-lanes x 4 batch-groups
#define VSTR 10        // smem row stride (floats): float2-aligned, 2-way conflicts max

// ---------------- device scratch (static, no runtime allocation) -------------
__device__ float4 RPd[UNITS*UNITS];   // recurrent params {s, c, Wh, WEh}
__device__ float4 SPd[NIN*UNITS];     // sensory params
__device__ float  NSd[NBATCH*UNITS];  // sensory numerator term [b][j]
__device__ float  DSd[NBATCH*UNITS];  // sensory denominator term [b][j]
__device__ float  VBa[NBATCH*UNITS];  // v ping  [b][u]
__device__ float  VBb[NBATCH*UNITS];  // v pong  [b][u]
__device__ float  CGc_[UNITS];        // cm + gleak + sum_i Wh   (recurrent)
__device__ float  CNc_[UNITS];        // gleak*vleak + sum_i WEh (recurrent)
__device__ float  SWs_[UNITS];        // sum_i Wh   (sensory)
__device__ float  SWEs_[UNITS];       // sum_i WEh  (sensory)

// sigmoid(sigma*(v-mu)) = 0.5 + 0.5*tanh(0.5*sigma*v - 0.5*sigma*mu)
// act = W*sigmoid = Wh*tanh(u) + Wh with Wh = 0.5*W; the constant "+Wh" halves
// are folded into per-j column sums applied once in the epilogue.

__global__ void prep_r(const float* __restrict__ mu, const float* __restrict__ sg,
                       const float* __restrict__ W,  const float* __restrict__ er) {
    int idx = blockIdx.x*blockDim.x + threadIdx.x;
    if (idx < UNITS*UNITS) {
        float s = sg[idx], m = mu[idx], w = W[idx], e = er[idx];
        RPd[idx] = make_float4(0.5f*s, -0.5f*s*m, 0.5f*w, 0.5f*w*e);
    }
}

__global__ void prep_s(const float* __restrict__ mu, const float* __restrict__ sg,
                       const float* __restrict__ W,  const float* __restrict__ er) {
    int idx = blockIdx.x*blockDim.x + threadIdx.x;
    if (idx < NIN*UNITS) {
        float s = sg[idx], m = mu[idx], w = W[idx], e = er[idx];
        SPd[idx] = make_float4(0.5f*s, -0.5f*s*m, 0.5f*w, 0.5f*w*e);
    }
}

// coalesced column sums: lane = j, 8 i-rows per warp-row, smem reduce
__global__ __launch_bounds__(256) void colsums(const float* __restrict__ cm,
                                               const float* __restrict__ gl,
                                               const float* __restrict__ vl) {
    __shared__ float sm[8][32][4];
    int tx = threadIdx.x & 31;
    int ty = threadIdx.x >> 5;
    int j  = blockIdx.x*32 + tx;

    float rw = 0.f, rwe = 0.f, sw = 0.f, swe = 0.f;
    for (int i = ty; i < UNITS; i += 8) { float4 p = RPd[i*UNITS + j]; rw += p.z; rwe += p.w; }
    for (int i = ty; i < NIN;   i += 8) { float4 p = SPd[i*UNITS + j]; sw += p.z; swe += p.w; }
    sm[ty][tx][0] = rw; sm[ty][tx][1] = rwe; sm[ty][tx][2] = sw; sm[ty][tx][3] = swe;
    __syncthreads();
    if (ty == 0) {
        for (int r = 1; r < 8; r++) {
            rw += sm[r][tx][0]; rwe += sm[r][tx][1];
            sw += sm[r][tx][2]; swe += sm[r][tx][3];
        }
        SWs_[j]  = sw;
        SWEs_[j] = swe;
        CGc_[j]  = cm[j] + gl[j] + rw;
        CNc_[j]  = gl[j]*vl[j] + rwe;
    }
}

__device__ __forceinline__ float tanh_apx(float x) {
    float y;
    asm("tanh.approx.f32 %0, %1;" : "=f"(y) : "f"(x));
    return y;
}

// ---------------- sensory synapse sums ---------------------------------------
__global__ __launch_bounds__(NTHR) void sensory_k(const float* __restrict__ inp,
                                                  const float* __restrict__ iw,
                                                  const float* __restrict__ ib) {
    __shared__ float xs[NIN*VSTR];     // 10 KB
    int jbase = blockIdx.x * JT;
    int bbase = blockIdx.y * BT;
    int t = threadIdx.x;

    // stage x = inputs*input_w + input_b, transposed: xs[i*VSTR + b]
    for (int idx = t; idx < BT*NIN; idx += NTHR) {
        int b = idx >> 8;              // NIN = 256
        int i = idx & (NIN-1);
        xs[i*VSTR + b] = fmaf(inp[(bbase + b)*NIN + i], iw[i], ib[i]);
    }
    __syncthreads();

    int tx = t & 31;
    int bg = t >> 5;                   // 0..3, warp-uniform
    int j  = jbase + tx;

    const float4* __restrict__ rp = SPd + j;
    float num0 = 0.f, num1 = 0.f, den0 = 0.f, den1 = 0.f;

    #pragma unroll 8
    for (int i = 0; i < NIN; i++) {
        float4 p  = rp[(size_t)i*UNITS];
        float2 vv = *reinterpret_cast<const float2*>(xs + i*VSTR + bg*NB);
        float h0 = tanh_apx(fmaf(p.x, vv.x, p.y));
        float h1 = tanh_apx(fmaf(p.x, vv.y, p.y));
        den0 = fmaf(p.z, h0, den0); num0 = fmaf(p.w, h0, num0);
        den1 = fmaf(p.z, h1, den1); num1 = fmaf(p.w, h1, num1);
    }

    float sw = SWs_[j], swe = SWEs_[j];
    int b0 = bbase + bg*NB;
    NSd[b0*UNITS + j]       = num0 + swe;
    DSd[b0*UNITS + j]       = den0 + sw;
    NSd[(b0 + 1)*UNITS + j] = num1 + swe;
    DSd[(b0 + 1)*UNITS + j] = den1 + sw;
}

// ---------------- one ODE unfold step -----------------------------------------
__global__ __launch_bounds__(NTHR) void unfold_k(const float* __restrict__ vext,
                                                 const float* __restrict__ cm,
                                                 float* __restrict__ dout,
                                                 int in_sel, int out_sel) {
    __shared__ float vs[UNITS*VSTR];   // 20 KB
    const float* vin = (in_sel  == 0) ? vext : (in_sel  == 1 ? VBa : VBb);
    float*      vout = (out_sel == 0) ? dout : (out_sel == 1 ? VBa : VBb);

    int jbase = blockIdx.x * JT;
    int bbase = blockIdx.y * BT;
    int t = threadIdx.x;

    // stage v transposed: vs[i*VSTR + b]
    for (int idx = t; idx < BT*UNITS; idx += NTHR) {
        int b = idx >> 9;              // UNITS = 512
        int i = idx & (UNITS-1);
        vs[i*VSTR + b] = vin[(bbase + b)*UNITS + i];
    }
    __syncthreads();

    int tx = t & 31;
    int bg = t >> 5;                   // 0..3, warp-uniform
    int j  = jbase + tx;

    const float4* __restrict__ rp = RPd + j;
    float num0 = 0.f, num1 = 0.f, den0 = 0.f, den1 = 0.f;

    #pragma unroll 8
    for (int i = 0; i < UNITS; i++) {
        float4 p  = rp[(size_t)i*UNITS];
        float2 vv = *reinterpret_cast<const float2*>(vs + i*VSTR + bg*NB);
        float h0 = tanh_apx(fmaf(p.x, vv.x, p.y));
        float h1 = tanh_apx(fmaf(p.x, vv.y, p.y));
        den0 = fmaf(p.z, h0, den0); num0 = fmaf(p.w, h0, num0);
        den1 = fmaf(p.z, h1, den1); num1 = fmaf(p.w, h1, num1);
    }

    float cgj = CGc_[j], cnj = CNc_[j], cmj = cm[j];
    int b0 = bbase + bg*NB;
    float vp0 = vs[j*VSTR + bg*NB];
    float vp1 = vs[j*VSTR + bg*NB + 1];
    float numer0 = fmaf(cmj, vp0, cnj + NSd[b0*UNITS + j] + num0);
    float denom0 = cgj + DSd[b0*UNITS + j] + den0;
    float numer1 = fmaf(cmj, vp1, cnj + NSd[(b0 + 1)*UNITS + j] + num1);
    float denom1 = cgj + DSd[(b0 + 1)*UNITS + j] + den1;
    vout[b0*UNITS + j]       = __fdividef(numer0, denom0);
    vout[(b0 + 1)*UNITS + j] = __fdividef(numer1, denom1);
}

// ---------------- launch ------------------------------------------------------
extern "C" void kernel_launch(void* const* d_in, const int* in_sizes, int n_in,
                              void* d_out, int out_size) {
    const float* inputs = (const float*)d_in[0];
    const float* state  = (const float*)d_in[1];
    const float* iw     = (const float*)d_in[2];
    const float* ib     = (const float*)d_in[3];
    const float* smu    = (const float*)d_in[4];
    const float* ssig   = (const float*)d_in[5];
    const float* sW     = (const float*)d_in[6];
    const float* serev  = (const float*)d_in[7];
    const float* rmu    = (const float*)d_in[8];
    const float* rsig   = (const float*)d_in[9];
    const float* rW     = (const float*)d_in[10];
    const float* rerev  = (const float*)d_in[11];
    const float* vleak  = (const float*)d_in[12];
    const float* gleak  = (const float*)d_in[13];
    const float* cm     = (const float*)d_in[14];
    float* out = (float*)d_out;

    prep_r<<<(UNITS*UNITS + 255)/256, 256>>>(rmu, rsig, rW, rerev);
    prep_s<<<(NIN*UNITS + 255)/256, 256>>>(smu, ssig, sW, serev);
    colsums<<<UNITS/32, 256>>>(cm, gleak, vleak);

    dim3 grid(UNITS/JT, NBATCH/BT);   // 16 x 64 = 1024 CTAs
    sensory_k<<<grid, NTHR>>>(inputs, iw, ib);

    // 6 unfolds: state -> VBa -> VBb -> VBa -> VBb -> VBa -> d_out
    unfold_k<<<grid, NTHR>>>(state,   cm, nullptr, 0, 1);
    unfold_k<<<grid, NTHR>>>(nullptr, cm, nullptr, 1, 2);
    unfold_k<<<grid, NTHR>>>(nullptr, cm, nullptr, 2, 1);
    unfold_k<<<grid, NTHR>>>(nullptr, cm, nullptr, 1, 2);
    unfold_k<<<grid, NTHR>>>(nullptr, cm, nullptr, 2, 1);
    unfold_k<<<grid, NTHR>>>(nullptr, cm, out,     1, 0);
}

// round 6
// speedup vs baseline: 1.2273x; 1.2273x over previous
#include <cuda_runtime.h>
#include <cstdint>

#define UNITS  512
#define NIN    256
#define NBATCH 512
#define JT 32          // j-columns per CTA
#define BT 16          // batches per CTA
#define NB 4           // batches per thread
#define NTHR 128
#define VSTR 20        // smem row stride (floats): float4-aligned, broadcast reads
#define CH 8           // prefetch chunk (param float4s in flight)

// ---------------- device scratch (static, no runtime allocation) -------------
__device__ float4 RPd[UNITS*UNITS];   // recurrent params {s, c, Wh, WEh}
__device__ float4 SPd[NIN*UNITS];     // sensory params
__device__ float2 PP0[NBATCH*UNITS];  // partial (num,den), i-half 0
__device__ float2 PP1[NBATCH*UNITS];  // partial (num,den), i-half 1
__device__ float  NSd[NBATCH*UNITS];  // sensory numerator term [b][j]
__device__ float  DSd[NBATCH*UNITS];  // sensory denominator term [b][j]
__device__ float  VBa[NBATCH*UNITS];  // v ping  [b][u]
__device__ float  VBb[NBATCH*UNITS];  // v pong  [b][u]
__device__ float  CGc_[UNITS];        // cm + gleak + sum_i Wh   (recurrent)
__device__ float  CNc_[UNITS];        // gleak*vleak + sum_i WEh (recurrent)
__device__ float  SWs_[UNITS];        // sum_i Wh   (sensory)
__device__ float  SWEs_[UNITS];       // sum_i WEh  (sensory)

// sigmoid(sigma*(v-mu)) = 0.5 + 0.5*tanh(0.5*sigma*v - 0.5*sigma*mu)
// act = W*sigmoid = Wh*tanh(u) + Wh with Wh = 0.5*W; constant "+Wh" halves are
// folded into per-j column sums applied once in the combine epilogue.

__global__ void prep_r(const float* __restrict__ mu, const float* __restrict__ sg,
                       const float* __restrict__ W,  const float* __restrict__ er) {
    int idx = blockIdx.x*blockDim.x + threadIdx.x;
    if (idx < UNITS*UNITS) {
        float s = sg[idx], m = mu[idx], w = W[idx], e = er[idx];
        RPd[idx] = make_float4(0.5f*s, -0.5f*s*m, 0.5f*w, 0.5f*w*e);
    }
}

__global__ void prep_s(const float* __restrict__ mu, const float* __restrict__ sg,
                       const float* __restrict__ W,  const float* __restrict__ er) {
    int idx = blockIdx.x*blockDim.x + threadIdx.x;
    if (idx < NIN*UNITS) {
        float s = sg[idx], m = mu[idx], w = W[idx], e = er[idx];
        SPd[idx] = make_float4(0.5f*s, -0.5f*s*m, 0.5f*w, 0.5f*w*e);
    }
}

// coalesced column sums: lane = j, 8 i-rows per warp-row, smem reduce
__global__ __launch_bounds__(256) void colsums(const float* __restrict__ cm,
                                               const float* __restrict__ gl,
                                               const float* __restrict__ vl) {
    __shared__ float sm[8][32][4];
    int tx = threadIdx.x & 31;
    int ty = threadIdx.x >> 5;
    int j  = blockIdx.x*32 + tx;

    float rw = 0.f, rwe = 0.f, sw = 0.f, swe = 0.f;
    for (int i = ty; i < UNITS; i += 8) { float4 p = RPd[i*UNITS + j]; rw += p.z; rwe += p.w; }
    for (int i = ty; i < NIN;   i += 8) { float4 p = SPd[i*UNITS + j]; sw += p.z; swe += p.w; }
    sm[ty][tx][0] = rw; sm[ty][tx][1] = rwe; sm[ty][tx][2] = sw; sm[ty][tx][3] = swe;
    __syncthreads();
    if (ty == 0) {
        for (int r = 1; r < 8; r++) {
            rw += sm[r][tx][0]; rwe += sm[r][tx][1];
            sw += sm[r][tx][2]; swe += sm[r][tx][3];
        }
        SWs_[j]  = sw;
        SWEs_[j] = swe;
        CGc_[j]  = cm[j] + gl[j] + rw;
        CNc_[j]  = gl[j]*vl[j] + rwe;
    }
}

__device__ __forceinline__ float tanh_apx(float x) {
    float y;
    asm("tanh.approx.f32 %0, %1;" : "=f"(y) : "f"(x));
    return y;
}

// ---------------- sensory partials (i-half per blockIdx.z) --------------------
__global__ __launch_bounds__(NTHR) void sensory_k(const float* __restrict__ inp,
                                                  const float* __restrict__ iw,
                                                  const float* __restrict__ ib) {
    __shared__ float xs[(NIN/2)*VSTR];   // 10 KB
    const int IH = NIN/2;                // 128
    int jbase = blockIdx.x * JT;
    int bbase = blockIdx.y * BT;
    int ih    = blockIdx.z;              // 0 or 1
    int t = threadIdx.x;

    // stage x = inputs*input_w + input_b, transposed: xs[il*VSTR + b]
    for (int idx = t; idx < BT*IH; idx += NTHR) {
        int b  = idx >> 7;               // IH = 128
        int il = idx & (IH-1);
        int i  = ih*IH + il;
        xs[il*VSTR + b] = fmaf(inp[(bbase + b)*NIN + i], iw[i], ib[i]);
    }
    __syncthreads();

    int tx = t & 31;
    int bg = t >> 5;                     // warp-uniform
    int j  = jbase + tx;

    const float4* __restrict__ rp = SPd + (size_t)ih*IH*UNITS + j;
    float num0=0.f,num1=0.f,num2=0.f,num3=0.f;
    float den0=0.f,den1=0.f,den2=0.f,den3=0.f;

    float4 PA[CH], PB[CH];
    #pragma unroll
    for (int k = 0; k < CH; k++) PA[k] = rp[(size_t)k*UNITS];

    const int NC = IH/CH;                // 16 chunks
    #pragma unroll 1
    for (int c = 0; c < NC; c += 2) {
        { const float4* q = rp + (size_t)(c+1)*CH*UNITS;
          #pragma unroll
          for (int k = 0; k < CH; k++) PB[k] = q[(size_t)k*UNITS]; }
        #pragma unroll
        for (int k = 0; k < CH; k++) {
            float4 p  = PA[k];
            float4 vv = *reinterpret_cast<const float4*>(xs + (c*CH + k)*VSTR + bg*NB);
            float h0 = tanh_apx(fmaf(p.x, vv.x, p.y));
            float h1 = tanh_apx(fmaf(p.x, vv.y, p.y));
            float h2 = tanh_apx(fmaf(p.x, vv.z, p.y));
            float h3 = tanh_apx(fmaf(p.x, vv.w, p.y));
            den0 = fmaf(p.z, h0, den0); num0 = fmaf(p.w, h0, num0);
            den1 = fmaf(p.z, h1, den1); num1 = fmaf(p.w, h1, num1);
            den2 = fmaf(p.z, h2, den2); num2 = fmaf(p.w, h2, num2);
            den3 = fmaf(p.z, h3, den3); num3 = fmaf(p.w, h3, num3);
        }
        { int cn = (c + 2 < NC) ? (c + 2) : 0;
          const float4* q = rp + (size_t)cn*CH*UNITS;
          #pragma unroll
          for (int k = 0; k < CH; k++) PA[k] = q[(size_t)k*UNITS]; }
        #pragma unroll
        for (int k = 0; k < CH; k++) {
            float4 p  = PB[k];
            float4 vv = *reinterpret_cast<const float4*>(xs + ((c+1)*CH + k)*VSTR + bg*NB);
            float h0 = tanh_apx(fmaf(p.x, vv.x, p.y));
            float h1 = tanh_apx(fmaf(p.x, vv.y, p.y));
            float h2 = tanh_apx(fmaf(p.x, vv.z, p.y));
            float h3 = tanh_apx(fmaf(p.x, vv.w, p.y));
            den0 = fmaf(p.z, h0, den0); num0 = fmaf(p.w, h0, num0);
            den1 = fmaf(p.z, h1, den1); num1 = fmaf(p.w, h1, num1);
            den2 = fmaf(p.z, h2, den2); num2 = fmaf(p.w, h2, num2);
            den3 = fmaf(p.z, h3, den3); num3 = fmaf(p.w, h3, num3);
        }
    }

    float2* __restrict__ pp = (ih == 0) ? PP0 : PP1;
    float nn[NB] = {num0,num1,num2,num3};
    float dd[NB] = {den0,den1,den2,den3};
    #pragma unroll
    for (int k = 0; k < NB; k++) {
        int b = bbase + bg*NB + k;
        pp[b*UNITS + j] = make_float2(nn[k], dd[k]);
    }
}

// combine sensory partials -> NSd/DSd (with column-sum constants folded in)
__global__ __launch_bounds__(256) void scombine_k() {
    int t = blockIdx.x*blockDim.x + threadIdx.x;   // one float4-group of j per thread
    int j4 = t & (UNITS/4 - 1);
    float4 p0a = reinterpret_cast<const float4*>(PP0)[t*2];
    float4 p0b = reinterpret_cast<const float4*>(PP0)[t*2 + 1];
    float4 p1a = reinterpret_cast<const float4*>(PP1)[t*2];
    float4 p1b = reinterpret_cast<const float4*>(PP1)[t*2 + 1];
    float4 swe = reinterpret_cast<const float4*>(SWEs_)[j4];
    float4 sw  = reinterpret_cast<const float4*>(SWs_)[j4];
    float4 ns, ds;
    ns.x = p0a.x + p1a.x + swe.x;  ds.x = p0a.y + p1a.y + sw.x;
    ns.y = p0a.z + p1a.z + swe.y;  ds.y = p0a.w + p1a.w + sw.y;
    ns.z = p0b.x + p1b.x + swe.z;  ds.z = p0b.y + p1b.y + sw.z;
    ns.w = p0b.z + p1b.z + swe.w;  ds.w = p0b.w + p1b.w + sw.w;
    reinterpret_cast<float4*>(NSd)[t] = ns;
    reinterpret_cast<float4*>(DSd)[t] = ds;
}

// ---------------- unfold partials (i-half per blockIdx.z) ---------------------
__global__ __launch_bounds__(NTHR) void unfold_k(const float* __restrict__ vext,
                                                 int in_sel) {
    __shared__ float vs[(UNITS/2)*VSTR];  // 20 KB
    const int IH = UNITS/2;               // 256
    const float* vin = (in_sel == 0) ? vext : (in_sel == 1 ? VBa : VBb);

    int jbase = blockIdx.x * JT;
    int bbase = blockIdx.y * BT;
    int ih    = blockIdx.z;
    int t = threadIdx.x;

    // stage v transposed: vs[il*VSTR + b]
    for (int idx = t; idx < BT*IH; idx += NTHR) {
        int b  = idx >> 8;                // IH = 256
        int il = idx & (IH-1);
        vs[il*VSTR + b] = vin[(bbase + b)*UNITS + ih*IH + il];
    }
    __syncthreads();

    int tx = t & 31;
    int bg = t >> 5;
    int j  = jbase + tx;

    const float4* __restrict__ rp = RPd + (size_t)ih*IH*UNITS + j;
    float num0=0.f,num1=0.f,num2=0.f,num3=0.f;
    float den0=0.f,den1=0.f,den2=0.f,den3=0.f;

    float4 PA[CH], PB[CH];
    #pragma unroll
    for (int k = 0; k < CH; k++) PA[k] = rp[(size_t)k*UNITS];

    const int NC = IH/CH;                 // 32 chunks
    #pragma unroll 1
    for (int c = 0; c < NC; c += 2) {
        { const float4* q = rp + (size_t)(c+1)*CH*UNITS;
          #pragma unroll
          for (int k = 0; k < CH; k++) PB[k] = q[(size_t)k*UNITS]; }
        #pragma unroll
        for (int k = 0; k < CH; k++) {
            float4 p  = PA[k];
            float4 vv = *reinterpret_cast<const float4*>(vs + (c*CH + k)*VSTR + bg*NB);
            float h0 = tanh_apx(fmaf(p.x, vv.x, p.y));
            float h1 = tanh_apx(fmaf(p.x, vv.y, p.y));
            float h2 = tanh_apx(fmaf(p.x, vv.z, p.y));
            float h3 = tanh_apx(fmaf(p.x, vv.w, p.y));
            den0 = fmaf(p.z, h0, den0); num0 = fmaf(p.w, h0, num0);
            den1 = fmaf(p.z, h1, den1); num1 = fmaf(p.w, h1, num1);
            den2 = fmaf(p.z, h2, den2); num2 = fmaf(p.w, h2, num2);
            den3 = fmaf(p.z, h3, den3); num3 = fmaf(p.w, h3, num3);
        }
        { int cn = (c + 2 < NC) ? (c + 2) : 0;
          const float4* q = rp + (size_t)cn*CH*UNITS;
          #pragma unroll
          for (int k = 0; k < CH; k++) PA[k] = q[(size_t)k*UNITS]; }
        #pragma unroll
        for (int k = 0; k < CH; k++) {
            float4 p  = PB[k];
            float4 vv = *reinterpret_cast<const float4*>(vs + ((c+1)*CH + k)*VSTR + bg*NB);
            float h0 = tanh_apx(fmaf(p.x, vv.x, p.y));
            float h1 = tanh_apx(fmaf(p.x, vv.y, p.y));
            float h2 = tanh_apx(fmaf(p.x, vv.z, p.y));
            float h3 = tanh_apx(fmaf(p.x, vv.w, p.y));
            den0 = fmaf(p.z, h0, den0); num0 = fmaf(p.w, h0, num0);
            den1 = fmaf(p.z, h1, den1); num1 = fmaf(p.w, h1, num1);
            den2 = fmaf(p.z, h2, den2); num2 = fmaf(p.w, h2, num2);
            den3 = fmaf(p.z, h3, den3); num3 = fmaf(p.w, h3, num3);
        }
    }

    float2* __restrict__ pp = (ih == 0) ? PP0 : PP1;
    float nn[NB] = {num0,num1,num2,num3};
    float dd[NB] = {den0,den1,den2,den3};
    #pragma unroll
    for (int k = 0; k < NB; k++) {
        int b = bbase + bg*NB + k;
        pp[b*UNITS + j] = make_float2(nn[k], dd[k]);
    }
}

// combine: v' = (cm*v + CN + NS + num)/ (CG + DS + den), element-wise [b][j]
__global__ __launch_bounds__(256) void combine_k(const float* __restrict__ vext,
                                                 const float* __restrict__ cm,
                                                 float* __restrict__ dout,
                                                 int in_sel, int out_sel) {
    const float* vin  = (in_sel  == 0) ? vext : (in_sel  == 1 ? VBa : VBb);
    float*       vout = (out_sel == 0) ? dout : (out_sel == 1 ? VBa : VBb);

    int t = blockIdx.x*blockDim.x + threadIdx.x;   // one float4-group of j
    int j4 = t & (UNITS/4 - 1);
    float4 vp  = reinterpret_cast<const float4*>(vin)[t];
    float4 p0a = reinterpret_cast<const float4*>(PP0)[t*2];
    float4 p0b = reinterpret_cast<const float4*>(PP0)[t*2 + 1];
    float4 p1a = reinterpret_cast<const float4*>(PP1)[t*2];
    float4 p1b = reinterpret_cast<const float4*>(PP1)[t*2 + 1];
    float4 ns  = reinterpret_cast<const float4*>(NSd)[t];
    float4 ds  = reinterpret_cast<const float4*>(DSd)[t];
    float4 cg  = reinterpret_cast<const float4*>(CGc_)[j4];
    float4 cn  = reinterpret_cast<const float4*>(CNc_)[j4];
    float4 cmv = reinterpret_cast<const float4*>(cm)[j4];

    float4 r;
    r.x = __fdividef(fmaf(cmv.x, vp.x, cn.x + ns.x + p0a.x + p1a.x),
                     cg.x + ds.x + p0a.y + p1a.y);
    r.y = __fdividef(fmaf(cmv.y, vp.y, cn.y + ns.y + p0a.z + p1a.z),
                     cg.y + ds.y + p0a.w + p1a.w);
    r.z = __fdividef(fmaf(cmv.z, vp.z, cn.z + ns.z + p0b.x + p1b.x),
                     cg.z + ds.z + p0b.y + p1b.y);
    r.w = __fdividef(fmaf(cmv.w, vp.w, cn.w + ns.w + p0b.z + p1b.z),
                     cg.w + ds.w + p0b.w + p1b.w);
    reinterpret_cast<float4*>(vout)[t] = r;
}

// ---------------- launch ------------------------------------------------------
extern "C" void kernel_launch(void* const* d_in, const int* in_sizes, int n_in,
                              void* d_out, int out_size) {
    const float* inputs = (const float*)d_in[0];
    const float* state  = (const float*)d_in[1];
    const float* iw     = (const float*)d_in[2];
    const float* ib     = (const float*)d_in[3];
    const float* smu    = (const float*)d_in[4];
    const float* ssig   = (const float*)d_in[5];
    const float* sW     = (const float*)d_in[6];
    const float* serev  = (const float*)d_in[7];
    const float* rmu    = (const float*)d_in[8];
    const float* rsig   = (const float*)d_in[9];
    const float* rW     = (const float*)d_in[10];
    const float* rerev  = (const float*)d_in[11];
    const float* vleak  = (const float*)d_in[12];
    const float* gleak  = (const float*)d_in[13];
    const float* cm     = (const float*)d_in[14];
    float* out = (float*)d_out;

    prep_r<<<(UNITS*UNITS + 255)/256, 256>>>(rmu, rsig, rW, rerev);
    prep_s<<<(NIN*UNITS + 255)/256, 256>>>(smu, ssig, sW, serev);
    colsums<<<UNITS/32, 256>>>(cm, gleak, vleak);

    dim3 grid(UNITS/JT, NBATCH/BT, 2);   // 16 x 32 x 2 = 1024 CTAs
    const int CGRID = NBATCH*UNITS/4/256;  // 256 CTAs for combines

    sensory_k<<<grid, NTHR>>>(inputs, iw, ib);
    scombine_k<<<CGRID, 256>>>();

    // 6 unfolds: state -> VBa -> VBb -> VBa -> VBb -> VBa -> d_out
    unfold_k<<<grid, NTHR>>>(state, 0);
    combine_k<<<CGRID, 256>>>(state, cm, nullptr, 0, 1);
    unfold_k<<<grid, NTHR>>>(nullptr, 1);
    combine_k<<<CGRID, 256>>>(nullptr, cm, nullptr, 1, 2);
    unfold_k<<<grid, NTHR>>>(nullptr, 2);
    combine_k<<<CGRID, 256>>>(nullptr, cm, nullptr, 2, 1);
    unfold_k<<<grid, NTHR>>>(nullptr, 1);
    combine_k<<<CGRID, 256>>>(nullptr, cm, nullptr, 1, 2);
    unfold_k<<<grid, NTHR>>>(nullptr, 2);
    combine_k<<<CGRID, 256>>>(nullptr, cm, nullptr, 2, 1);
    unfold_k<<<grid, NTHR>>>(nullptr, 1);
    combine_k<<<CGRID, 256>>>(nullptr, cm, out, 1, 0);
}